// round 9
// baseline (speedup 1.0000x reference)
#include <cuda_runtime.h>
#include <cuda_bf16.h>
#include <math_constants.h>
#include <cstdint>

#define S_ 16384
#define K_ 4096
#define D_ 64
#define TEMP_ 50.0f
#define MAXEFF_ 5000.0f

// ---------------- scratch ----------------
__device__ unsigned int g_pmax[S_];
__device__ unsigned int g_nmax[S_];
// Fragment-packed tf32 splits {hi(t), hi(t+4), lo(t), lo(t+4)}:
__device__ float4 g_Xp[(size_t)S_ * 32];   // [row][d-slab][t]  (pass2 aff A)
__device__ float4 g_Yp1[K_ * 32];          // [row][d-slab][t]  (pass2 aff B)
__device__ float4 g_Yt2[D_ * (K_ / 8) * 4];// [d][k-slab][t]    (pass2 gemm2 B)
// hi-only tables for pass1 {hi(t), hi(t+4)}:
__device__ float2 g_Xh[(size_t)S_ * 32];
__device__ float2 g_Yh[K_ * 32];

#define NX  (S_ * 32)
#define NYA (K_ * 32)
#define NYT (D_ * (K_ / 8) * 4)

__device__ __forceinline__ unsigned int encf(float f) {
    unsigned int u = __float_as_uint(f);
    return (u & 0x80000000u) ? ~u : (u | 0x80000000u);
}
__device__ __forceinline__ float decf(unsigned int u) {
    return (u & 0x80000000u) ? __uint_as_float(u ^ 0x80000000u)
                             : __uint_as_float(~u);
}

__device__ __forceinline__ float tf32r(float x) {
    uint32_t u;
    asm("cvt.rna.tf32.f32 %0, %1;" : "=r"(u) : "f"(x));
    return __uint_as_float(u);
}
__device__ __forceinline__ void split1(float x, float& h, float& l) {
    h = tf32r(x);
    l = tf32r(x - h);
}
__device__ __forceinline__ float ex2(float x) {
    float r; asm("ex2.approx.ftz.f32 %0, %1;" : "=f"(r) : "f"(x)); return r;
}

__device__ __forceinline__ void mma8(float* c, const uint32_t* a,
                                     uint32_t b0, uint32_t b1) {
    asm volatile(
        "mma.sync.aligned.m16n8k8.row.col.f32.tf32.tf32.f32 "
        "{%0,%1,%2,%3}, {%4,%5,%6,%7}, {%8,%9}, {%0,%1,%2,%3};"
        : "+f"(c[0]), "+f"(c[1]), "+f"(c[2]), "+f"(c[3])
        : "r"(a[0]), "r"(a[1]), "r"(a[2]), "r"(a[3]), "r"(b0), "r"(b1));
}

// ---------------------------------------------------------------------------
// k_prep: packed split tables.
// ---------------------------------------------------------------------------
__global__ __launch_bounds__(256) void k_prep(
    const float* __restrict__ X, const float* __restrict__ Yw)
{
    const int i = blockIdx.x * 256 + threadIdx.x;
    if (i < NX) {
        int r = i >> 5, s = (i >> 2) & 7, t = i & 3;
        float h0, l0, h1, l1;
        split1(X[r * D_ + 8 * s + t],     h0, l0);
        split1(X[r * D_ + 8 * s + t + 4], h1, l1);
        g_Xp[i] = make_float4(h0, h1, l0, l1);
        g_Xh[i] = make_float2(h0, h1);
    } else if (i < NX + NYA) {
        int j = i - NX;
        int r = j >> 5, s = (j >> 2) & 7, t = j & 3;
        float h0, l0, h1, l1;
        split1(Yw[r * D_ + 8 * s + t],     h0, l0);
        split1(Yw[r * D_ + 8 * s + t + 4], h1, l1);
        g_Yp1[j] = make_float4(h0, h1, l0, l1);
        g_Yh[j]  = make_float2(h0, h1);
    } else {
        int j = i - NX - NYA;
        int d = j >> 11, s = (j >> 2) & 511, t = j & 3;
        float h0, l0, h1, l1;
        split1(Yw[(8 * s + t) * D_ + d],     h0, l0);
        split1(Yw[(8 * s + t + 4) * D_ + d], h1, l1);
        g_Yt2[j] = make_float4(h0, h1, l0, l1);
    }
}

// ---------------------------------------------------------------------------
// k_pass1: row max/min of aff via 1x tf32 (no store of aff).
// CTA 128x128, 256 thr, hi-only operands, 72KB smem, 2 CTA/SM.
// ---------------------------------------------------------------------------
__global__ __launch_bounds__(256, 2) void k_pass1(const float* __restrict__ icpt)
{
    extern __shared__ float2 sp2[];
    float2* Ah = sp2;               // [128][36]
    float2* Bh = sp2 + 128 * 36;    // [128][36]

    const int tid = threadIdx.x;
    const int lane = tid & 31, wid = tid >> 5;
    const int wrow = (wid & 3) * 32;
    const int wn = (wid >> 2) * 64;
    const int g = lane >> 2, t = lane & 3;
    const int r0 = blockIdx.y * 128, c0 = blockIdx.x * 128;

    #pragma unroll
    for (int j = 0; j < 16; j++) {
        int f = tid + j * 256;
        int row = f >> 5, w = f & 31;
        Ah[row * 36 + w] = g_Xh[(size_t)(r0 + row) * 32 + w];
        Bh[row * 36 + w] = g_Yh[(c0 + row) * 32 + w];
    }
    __syncthreads();

    float acc[2][8][4];
    #pragma unroll
    for (int mt = 0; mt < 2; mt++)
        #pragma unroll
        for (int nt = 0; nt < 8; nt++)
            #pragma unroll
            for (int q = 0; q < 4; q++) acc[mt][nt][q] = 0.0f;

    #pragma unroll
    for (int s = 0; s < 8; s++) {
        uint32_t a_[2][4];
        #pragma unroll
        for (int mt = 0; mt < 2; mt++) {
            const int rb = wrow + mt * 16;
            float2 p0 = Ah[(rb + g) * 36 + s * 4 + t];
            float2 p1 = Ah[(rb + 8 + g) * 36 + s * 4 + t];
            a_[mt][0] = __float_as_uint(p0.x);
            a_[mt][1] = __float_as_uint(p1.x);
            a_[mt][2] = __float_as_uint(p0.y);
            a_[mt][3] = __float_as_uint(p1.y);
        }
        #pragma unroll
        for (int nt = 0; nt < 8; nt++) {
            float2 b = Bh[(wn + nt * 8 + g) * 36 + s * 4 + t];
            #pragma unroll
            for (int mt = 0; mt < 2; mt++)
                mma8(acc[mt][nt], a_[mt],
                     __float_as_uint(b.x), __float_as_uint(b.y));
        }
    }

    float mx[4] = {-CUDART_INF_F, -CUDART_INF_F, -CUDART_INF_F, -CUDART_INF_F};
    float mn[4] = { CUDART_INF_F,  CUDART_INF_F,  CUDART_INF_F,  CUDART_INF_F};

    #pragma unroll
    for (int mt = 0; mt < 2; mt++) {
        #pragma unroll
        for (int nt = 0; nt < 8; nt++) {
            const int c = c0 + wn + nt * 8 + 2 * t;
            float2 ic = __ldg((const float2*)(icpt + c));
            float o0 = acc[mt][nt][0] - ic.x;
            float o1 = acc[mt][nt][1] - ic.y;
            float o2 = acc[mt][nt][2] - ic.x;
            float o3 = acc[mt][nt][3] - ic.y;
            mx[mt*2]   = fmaxf(mx[mt*2],   fmaxf(o0, o1));
            mn[mt*2]   = fminf(mn[mt*2],   fminf(o0, o1));
            mx[mt*2+1] = fmaxf(mx[mt*2+1], fmaxf(o2, o3));
            mn[mt*2+1] = fminf(mn[mt*2+1], fminf(o2, o3));
        }
    }
    #pragma unroll
    for (int m = 1; m < 4; m <<= 1) {
        #pragma unroll
        for (int i = 0; i < 4; i++) {
            mx[i] = fmaxf(mx[i], __shfl_xor_sync(0xffffffffu, mx[i], m));
            mn[i] = fminf(mn[i], __shfl_xor_sync(0xffffffffu, mn[i], m));
        }
    }
    if (t == 0) {
        #pragma unroll
        for (int mt = 0; mt < 2; mt++) {
            const int row = r0 + wrow + mt * 16 + g;
            atomicMax(&g_pmax[row],     encf(mx[mt*2]));
            atomicMax(&g_nmax[row],     encf(-mn[mt*2]));
            atomicMax(&g_pmax[row + 8], encf(mx[mt*2+1]));
            atomicMax(&g_nmax[row + 8], encf(-mn[mt*2+1]));
        }
    }
}

// ---------------------------------------------------------------------------
// k_pass2: fused. Per CTA: 128 rows. Stream 64 chunks of 64 k:
//   phase A: aff chunk = X@Y^T (3x tf32, registers) -icpt, exp, z/v,
//            split -> W smem (packed A-frag layout); stage YT(ck).
//   phase B: choice += w @ Y (3x tf32); stage YB(ck+1).
// ---------------------------------------------------------------------------
__global__ __launch_bounds__(256, 1) void k_pass2(
    const float* __restrict__ icpt,
    float* __restrict__ out_choice, float* __restrict__ out_v)
{
    extern __shared__ float4 s4[];
    float4* XA = s4;                  // [128][33]
    float4* YB = s4 + 128 * 33;       // [64][33]
    float4* YT = YB + 64 * 33;        // [64][33]
    float4* W  = YT + 64 * 33;        // [128][33]
    float*  Zb = (float*)(W + 128 * 33);  // [2][128]
    float*  Vb = Zb + 256;                // [2][128]

    const int tid = threadIdx.x;
    const int lane = tid & 31, wid = tid >> 5;
    const int wr = (wid & 3) * 32;
    const int wc = wid >> 2;          // 0/1
    const int g = lane >> 2, t = lane & 3;
    const int r0 = blockIdx.x * 128;

    const int rows[4] = {wr + g, wr + g + 8, wr + g + 16, wr + g + 24};
    float c1r[4], mr[4];
    #pragma unroll
    for (int i = 0; i < 4; i++) {
        float mxv = decf(g_pmax[r0 + rows[i]]);
        float mnv = -decf(g_nmax[r0 + rows[i]]);
        float span = fmaxf(mxv - mnv, 1e-3f);
        float tr = fminf(fmaxf(TEMP_ / span, TEMP_), MAXEFF_);
        c1r[i] = tr * 1.4426950408889634f;
        mr[i] = mxv;
    }

    // stage XA once (resident whole kernel)
    #pragma unroll
    for (int j = 0; j < 16; j++) {
        int f = tid + j * 256;
        int row = f >> 5, w = f & 31;
        XA[row * 33 + w] = g_Xp[(size_t)(r0 + row) * 32 + w];
    }
    // stage YB(0)
    #pragma unroll
    for (int j = 0; j < 8; j++) {
        int f = tid + j * 256;
        int row = f >> 5, w = f & 31;
        YB[row * 33 + w] = g_Yp1[row * 32 + w];
    }
    __syncthreads();

    float acc2[2][4][4];
    #pragma unroll
    for (int mt = 0; mt < 2; mt++)
        #pragma unroll
        for (int nt = 0; nt < 4; nt++)
            #pragma unroll
            for (int q = 0; q < 4; q++) acc2[mt][nt][q] = 0.0f;
    float zv[4] = {0, 0, 0, 0}, vv[4] = {0, 0, 0, 0};

    for (int ck = 0; ck < 64; ck++) {
        // ---- phase A: stage YT(ck); aff mma; epilogue -> W ----
        #pragma unroll
        for (int j = 0; j < 8; j++) {
            int f = tid + j * 256;
            int d = f >> 5, w = f & 31;
            int sl = w >> 2, tt = w & 3;
            YT[d * 33 + w] = g_Yt2[d * 2048 + (ck * 8 + sl) * 4 + tt];
        }

        float acc_a[2][4][4];
        #pragma unroll
        for (int mt = 0; mt < 2; mt++)
            #pragma unroll
            for (int nt = 0; nt < 4; nt++)
                #pragma unroll
                for (int q = 0; q < 4; q++) acc_a[mt][nt][q] = 0.0f;

        #pragma unroll
        for (int s = 0; s < 8; s++) {
            uint32_t ah[2][4], al[2][4];
            #pragma unroll
            for (int mt = 0; mt < 2; mt++) {
                const int rb = wr + mt * 16;
                uint4 q0 = *(const uint4*)&XA[(rb + g) * 33 + s * 4 + t];
                uint4 q1 = *(const uint4*)&XA[(rb + 8 + g) * 33 + s * 4 + t];
                ah[mt][0] = q0.x; ah[mt][1] = q1.x; ah[mt][2] = q0.y; ah[mt][3] = q1.y;
                al[mt][0] = q0.z; al[mt][1] = q1.z; al[mt][2] = q0.w; al[mt][3] = q1.w;
            }
            #pragma unroll
            for (int nt = 0; nt < 4; nt++) {
                uint4 bq = *(const uint4*)&YB[(wc * 32 + nt * 8 + g) * 33 + s * 4 + t];
                #pragma unroll
                for (int mt = 0; mt < 2; mt++) {
                    mma8(acc_a[mt][nt], ah[mt], bq.x, bq.y);
                    mma8(acc_a[mt][nt], ah[mt], bq.z, bq.w);
                    mma8(acc_a[mt][nt], al[mt], bq.x, bq.y);
                }
            }
        }

        // epilogue: -icpt, exp, z/v, split -> W
        const float2* icp = (const float2*)(icpt + ck * 64);
        #pragma unroll
        for (int mt = 0; mt < 2; mt++) {
            #pragma unroll
            for (int nt = 0; nt < 4; nt++) {
                float2 ic = __ldg(icp + wc * 16 + nt * 4 + t);
                const int sp = wc * 4 + nt;          // slab within chunk
                #pragma unroll
                for (int j = 0; j < 2; j++) {
                    const int ri = mt * 2 + j;
                    float a0 = acc_a[mt][nt][j * 2 + 0] - ic.x;
                    float a1 = acc_a[mt][nt][j * 2 + 1] - ic.y;
                    float e0 = ex2((a0 - mr[ri]) * c1r[ri]);
                    float e1 = ex2((a1 - mr[ri]) * c1r[ri]);
                    zv[ri] += e0 + e1;
                    vv[ri] = fmaf(e0, a0, fmaf(e1, a1, vv[ri]));
                    float h0, l0, h1, l1;
                    split1(e0, h0, l0);
                    split1(e1, h1, l1);
                    const int row = wr + mt * 16 + g + 8 * j;
                    float* wf = (float*)&W[row * 33 + sp * 4];
                    // t''=2t -> entry eidx=(2t)&3, comp offset ((2t)>>2)*2
                    const int t0 = 2 * t, t1 = 2 * t + 1;
                    *(float2*)(wf + (t0 & 3) * 4 + (t0 >> 2) * 2) = make_float2(h0, l0);
                    *(float2*)(wf + (t1 & 3) * 4 + (t1 >> 2) * 2) = make_float2(h1, l1);
                }
            }
        }
        __syncthreads();

        // ---- phase B: stage YB(ck+1); gemm2 mma ----
        if (ck + 1 < 64) {
            #pragma unroll
            for (int j = 0; j < 8; j++) {
                int f = tid + j * 256;
                int row = f >> 5, w = f & 31;
                YB[row * 33 + w] = g_Yp1[((ck + 1) * 64 + row) * 32 + w];
            }
        }
        #pragma unroll
        for (int s = 0; s < 8; s++) {
            uint32_t ah[2][4], al[2][4];
            #pragma unroll
            for (int mt = 0; mt < 2; mt++) {
                const int rb = wr + mt * 16;
                uint4 q0 = *(const uint4*)&W[(rb + g) * 33 + s * 4 + t];
                uint4 q1 = *(const uint4*)&W[(rb + 8 + g) * 33 + s * 4 + t];
                ah[mt][0] = q0.x; ah[mt][1] = q1.x; ah[mt][2] = q0.z; ah[mt][3] = q1.z;
                al[mt][0] = q0.y; al[mt][1] = q1.y; al[mt][2] = q0.w; al[mt][3] = q1.w;
            }
            #pragma unroll
            for (int nt = 0; nt < 4; nt++) {
                uint4 bq = *(const uint4*)&YT[(wc * 32 + nt * 8 + g) * 33 + s * 4 + t];
                #pragma unroll
                for (int mt = 0; mt < 2; mt++) {
                    mma8(acc2[mt][nt], ah[mt], bq.x, bq.y);
                    mma8(acc2[mt][nt], ah[mt], bq.z, bq.w);
                    mma8(acc2[mt][nt], al[mt], bq.x, bq.y);
                }
            }
        }
        __syncthreads();
    }

    // z/v butterfly over t lanes, then cross-wc via smem
    #pragma unroll
    for (int m = 1; m < 4; m <<= 1) {
        #pragma unroll
        for (int i = 0; i < 4; i++) {
            zv[i] += __shfl_xor_sync(0xffffffffu, zv[i], m);
            vv[i] += __shfl_xor_sync(0xffffffffu, vv[i], m);
        }
    }
    if (t == 0) {
        #pragma unroll
        for (int i = 0; i < 4; i++) {
            Zb[wc * 128 + rows[i]] = zv[i];
            Vb[wc * 128 + rows[i]] = vv[i];
        }
    }
    __syncthreads();

    float inv[4];
    #pragma unroll
    for (int i = 0; i < 4; i++) {
        float Z = Zb[rows[i]] + Zb[128 + rows[i]];
        inv[i] = 1.0f / Z;
        if (t == 0 && wc == 0)
            out_v[r0 + rows[i]] = (Vb[rows[i]] + Vb[128 + rows[i]]) / Z;
    }
    #pragma unroll
    for (int mt = 0; mt < 2; mt++) {
        #pragma unroll
        for (int nt = 0; nt < 4; nt++) {
            const int row = wr + mt * 16 + g;
            const int col = wc * 32 + nt * 8 + 2 * t;
            *(float2*)(out_choice + (size_t)(r0 + row) * D_ + col) =
                make_float2(acc2[mt][nt][0] * inv[mt*2],
                            acc2[mt][nt][1] * inv[mt*2]);
            *(float2*)(out_choice + (size_t)(r0 + row + 8) * D_ + col) =
                make_float2(acc2[mt][nt][2] * inv[mt*2+1],
                            acc2[mt][nt][3] * inv[mt*2+1]);
        }
    }
}

// ---------------------------------------------------------------------------
extern "C" void kernel_launch(void* const* d_in, const int* in_sizes, int n_in,
                              void* d_out, int out_size) {
    const float* X    = (const float*)d_in[0];
    const float* Yw   = (const float*)d_in[1];
    const float* icpt = (const float*)d_in[2];
    float* out        = (float*)d_out;
    float* out_choice = out;
    float* out_v      = out + (size_t)S_ * D_;

    const int smem1 = 2 * 128 * 36 * 8;                     // 73,728
    const int smem2 = (128*33 + 64*33 + 64*33 + 128*33) * 16 + 512 * 4; // 204,800
    cudaFuncSetAttribute(k_pass1, cudaFuncAttributeMaxDynamicSharedMemorySize, smem1);
    cudaFuncSetAttribute(k_pass2, cudaFuncAttributeMaxDynamicSharedMemorySize, smem2);

    k_prep<<<(NX + NYA + NYT) / 256, 256>>>(X, Yw);

    dim3 g1(K_ / 128, S_ / 128);
    k_pass1<<<g1, 256, smem1>>>(icpt);
    k_pass2<<<S_ / 128, 256, smem2>>>(icpt, out_choice, out_v);
}

// round 10
// speedup vs baseline: 1.1138x; 1.1138x over previous
#include <cuda_runtime.h>
#include <cuda_bf16.h>
#include <math_constants.h>
#include <cstdint>

#define S_ 16384
#define K_ 4096
#define D_ 64
#define TEMP_ 50.0f
#define MAXEFF_ 5000.0f

// ---------------- scratch ----------------
__device__ float        g_aff[(size_t)S_ * K_];
__device__ unsigned int g_pmax[S_];
__device__ unsigned int g_nmax[S_];
// Fragment-packed tf32 splits {hi(t), hi(t+4), lo(t), lo(t+4)}:
__device__ float4 g_Xp[(size_t)S_ * 32];    // [row][d-slab][t]
__device__ float4 g_Yp1[K_ * 32];           // [row][d-slab][t]
__device__ float4 g_Yt2[D_ * (K_ / 8) * 4]; // [d][k-slab][t]

#define NX  (S_ * 32)
#define NYA (K_ * 32)
#define NYT (D_ * (K_ / 8) * 4)

__device__ __forceinline__ unsigned int encf(float f) {
    unsigned int u = __float_as_uint(f);
    return (u & 0x80000000u) ? ~u : (u | 0x80000000u);
}
__device__ __forceinline__ float decf(unsigned int u) {
    return (u & 0x80000000u) ? __uint_as_float(u ^ 0x80000000u)
                             : __uint_as_float(~u);
}
__device__ __forceinline__ float tf32r(float x) {
    uint32_t u;
    asm("cvt.rna.tf32.f32 %0, %1;" : "=r"(u) : "f"(x));
    return __uint_as_float(u);
}
__device__ __forceinline__ void split1(float x, float& h, float& l) {
    h = tf32r(x);
    l = tf32r(x - h);
}
__device__ __forceinline__ float ex2(float x) {
    float r; asm("ex2.approx.ftz.f32 %0, %1;" : "=f"(r) : "f"(x)); return r;
}
__device__ __forceinline__ void mma8(float* c, const uint32_t* a,
                                     uint32_t b0, uint32_t b1) {
    asm volatile(
        "mma.sync.aligned.m16n8k8.row.col.f32.tf32.tf32.f32 "
        "{%0,%1,%2,%3}, {%4,%5,%6,%7}, {%8,%9}, {%0,%1,%2,%3};"
        : "+f"(c[0]), "+f"(c[1]), "+f"(c[2]), "+f"(c[3])
        : "r"(a[0]), "r"(a[1]), "r"(a[2]), "r"(a[3]), "r"(b0), "r"(b1));
}

// ---------------------------------------------------------------------------
// k_prep: packed split tables (R8-identical).
// ---------------------------------------------------------------------------
__global__ __launch_bounds__(256) void k_prep(
    const float* __restrict__ X, const float* __restrict__ Yw)
{
    const int i = blockIdx.x * 256 + threadIdx.x;
    if (i < NX) {
        int r = i >> 5, s = (i >> 2) & 7, t = i & 3;
        float h0, l0, h1, l1;
        split1(X[r * D_ + 8 * s + t],     h0, l0);
        split1(X[r * D_ + 8 * s + t + 4], h1, l1);
        g_Xp[i] = make_float4(h0, h1, l0, l1);
    } else if (i < NX + NYA) {
        int j = i - NX;
        int r = j >> 5, s = (j >> 2) & 7, t = j & 3;
        float h0, l0, h1, l1;
        split1(Yw[r * D_ + 8 * s + t],     h0, l0);
        split1(Yw[r * D_ + 8 * s + t + 4], h1, l1);
        g_Yp1[j] = make_float4(h0, h1, l0, l1);
    } else {
        int j = i - NX - NYA;
        int d = j >> 11, s = (j >> 2) & 511, t = j & 3;
        float h0, l0, h1, l1;
        split1(Yw[(8 * s + t) * D_ + d],     h0, l0);
        split1(Yw[(8 * s + t + 4) * D_ + d], h1, l1);
        g_Yt2[j] = make_float4(h0, h1, l0, l1);
    }
}

// ---------------------------------------------------------------------------
// GEMM1: aff = X @ Y^T - icpt. CTA 128x128, 512 thr (16 warps, 32x32 tiles).
// ---------------------------------------------------------------------------
__global__ __launch_bounds__(512, 1) void k_gemm1_tc(const float* __restrict__ icpt)
{
    extern __shared__ float4 sm4[];
    float4* As = sm4;                 // [128][36]
    float4* Bs = sm4 + 128 * 36;      // [128][36]

    const int tid = threadIdx.x;
    const int lane = tid & 31, wid = tid >> 5;
    const int wrow = (wid & 3) * 32;
    const int wn = (wid >> 2) * 32;
    const int g = lane >> 2, t = lane & 3;
    const int r0 = blockIdx.y * 128, c0 = blockIdx.x * 128;

    #pragma unroll
    for (int j = 0; j < 8; j++) {
        int f = tid + j * 512;
        int row = f >> 5, w = f & 31;
        As[row * 36 + w] = g_Xp[(size_t)(r0 + row) * 32 + w];
        Bs[row * 36 + w] = g_Yp1[(c0 + row) * 32 + w];
    }
    __syncthreads();

    float acc[2][4][4];
    #pragma unroll
    for (int mt = 0; mt < 2; mt++)
        #pragma unroll
        for (int nt = 0; nt < 4; nt++)
            #pragma unroll
            for (int q = 0; q < 4; q++) acc[mt][nt][q] = 0.0f;

    #pragma unroll
    for (int s = 0; s < 8; s++) {
        uint32_t ah[2][4], al[2][4];
        #pragma unroll
        for (int mt = 0; mt < 2; mt++) {
            const int rb = wrow + mt * 16;
            uint4 q0 = *(const uint4*)&As[(rb + g) * 36 + s * 4 + t];
            uint4 q1 = *(const uint4*)&As[(rb + 8 + g) * 36 + s * 4 + t];
            ah[mt][0] = q0.x; ah[mt][1] = q1.x; ah[mt][2] = q0.y; ah[mt][3] = q1.y;
            al[mt][0] = q0.z; al[mt][1] = q1.z; al[mt][2] = q0.w; al[mt][3] = q1.w;
        }
        #pragma unroll
        for (int nt = 0; nt < 4; nt++) {
            uint4 bq = *(const uint4*)&Bs[(wn + nt * 8 + g) * 36 + s * 4 + t];
            #pragma unroll
            for (int mt = 0; mt < 2; mt++) {
                mma8(acc[mt][nt], ah[mt], bq.x, bq.y);
                mma8(acc[mt][nt], ah[mt], bq.z, bq.w);
                mma8(acc[mt][nt], al[mt], bq.x, bq.y);
            }
        }
    }

    float mx[4] = {-CUDART_INF_F, -CUDART_INF_F, -CUDART_INF_F, -CUDART_INF_F};
    float mn[4] = { CUDART_INF_F,  CUDART_INF_F,  CUDART_INF_F,  CUDART_INF_F};

    #pragma unroll
    for (int mt = 0; mt < 2; mt++) {
        #pragma unroll
        for (int nt = 0; nt < 4; nt++) {
            const int c = c0 + wn + nt * 8 + 2 * t;
            float2 ic = __ldg((const float2*)(icpt + c));
            float o0 = acc[mt][nt][0] - ic.x;
            float o1 = acc[mt][nt][1] - ic.y;
            float o2 = acc[mt][nt][2] - ic.x;
            float o3 = acc[mt][nt][3] - ic.y;
            const int row = r0 + wrow + mt * 16 + g;
            *(float2*)(g_aff + (size_t)row * K_ + c)       = make_float2(o0, o1);
            *(float2*)(g_aff + (size_t)(row + 8) * K_ + c) = make_float2(o2, o3);
            mx[mt*2]   = fmaxf(mx[mt*2],   fmaxf(o0, o1));
            mn[mt*2]   = fminf(mn[mt*2],   fminf(o0, o1));
            mx[mt*2+1] = fmaxf(mx[mt*2+1], fmaxf(o2, o3));
            mn[mt*2+1] = fminf(mn[mt*2+1], fminf(o2, o3));
        }
    }
    #pragma unroll
    for (int m = 1; m < 4; m <<= 1) {
        #pragma unroll
        for (int i = 0; i < 4; i++) {
            mx[i] = fmaxf(mx[i], __shfl_xor_sync(0xffffffffu, mx[i], m));
            mn[i] = fminf(mn[i], __shfl_xor_sync(0xffffffffu, mn[i], m));
        }
    }
    if (t == 0) {
        #pragma unroll
        for (int mt = 0; mt < 2; mt++) {
            const int row = r0 + wrow + mt * 16 + g;
            atomicMax(&g_pmax[row],     encf(mx[mt*2]));
            atomicMax(&g_nmax[row],     encf(-mn[mt*2]));
            atomicMax(&g_pmax[row + 8], encf(mx[mt*2+1]));
            atomicMax(&g_nmax[row + 8], encf(-mn[mt*2+1]));
        }
    }
}

// ---------------------------------------------------------------------------
// k_soft: 512 thr = 4 k-groups x 4 row-warps (32 rows, all 64 d).
// 32-k chunks, 8 double-buffered B buffers; aff prefetch 1 step ahead.
// ---------------------------------------------------------------------------
__global__ __launch_bounds__(512, 1) void k_soft(
    float* __restrict__ out_choice, float* __restrict__ out_v)
{
    extern __shared__ float4 sb4[];   // 8 buffers x 1280 f4 ([64 d][20])

    const int tid = threadIdx.x;
    const int lane = tid & 31, wid = tid >> 5;
    const int grp = wid >> 2;                 // k-group 0..3
    const int wrow = (wid & 3) * 32;
    const int g = lane >> 2, t = lane & 3;
    const int r0 = blockIdx.x * 128;

    const int rows[4] = {wrow + g, wrow + g + 8, wrow + g + 16, wrow + g + 24};
    float c1r[4], mr[4];
    #pragma unroll
    for (int i = 0; i < 4; i++) {
        float mxv = decf(g_pmax[r0 + rows[i]]);
        float mnv = -decf(g_nmax[r0 + rows[i]]);
        float span = fmaxf(mxv - mnv, 1e-3f);
        float tr = fminf(fmaxf(TEMP_ / span, TEMP_), MAXEFF_);
        c1r[i] = tr * 1.4426950408889634f;
        mr[i] = mxv;
    }

    float acc2[2][8][4];
    #pragma unroll
    for (int mt = 0; mt < 2; mt++)
        #pragma unroll
        for (int nt = 0; nt < 8; nt++)
            #pragma unroll
            for (int q = 0; q < 4; q++) acc2[mt][nt][q] = 0.0f;
    float zv[4] = {0, 0, 0, 0}, vv[4] = {0, 0, 0, 0};

    // stage round R (4 chunks 4R+b -> buffers (b, par)); all 512 threads
    auto stage = [&](int R, int par) {
        #pragma unroll
        for (int j = 0; j < 8; j++) {
            int f = tid + j * 512;        // 0..4095
            int b = f >> 10, r = f & 1023;
            int d = r >> 4, w = r & 15;
            int c = 4 * R + b;
            sb4[(b * 2 + par) * 1280 + d * 20 + w] = g_Yt2[d * 2048 + c * 16 + w];
        }
    };

    // aff fragment load for this group's global step 0..127
    auto ldx = [&](int gstep, float* xa) {
        const int kk = (4 * (gstep >> 2) + grp) * 32 + (gstep & 3) * 8;
        #pragma unroll
        for (int mt = 0; mt < 2; mt++) {
            const float* a0 = g_aff + (size_t)(r0 + rows[mt*2])   * K_ + kk;
            const float* a1 = g_aff + (size_t)(r0 + rows[mt*2+1]) * K_ + kk;
            xa[mt*4+0] = __ldg(a0 + t);
            xa[mt*4+1] = __ldg(a1 + t);
            xa[mt*4+2] = __ldg(a0 + t + 4);
            xa[mt*4+3] = __ldg(a1 + t + 4);
        }
    };

    stage(0, 0);
    float xa[8], xb[8];
    ldx(0, xa);
    __syncthreads();

    for (int ss = 0; ss < 32; ss++) {
        const int cur = ss & 1;
        if (ss + 1 < 32) stage(ss + 1, cur ^ 1);
        const float4* B = sb4 + (grp * 2 + cur) * 1280;

        #pragma unroll
        for (int s = 0; s < 4; s++) {
            const int gstep = ss * 4 + s;
            if (gstep + 1 < 128) ldx(gstep + 1, xb);

            uint32_t ah[2][4], al[2][4];
            #pragma unroll
            for (int mt = 0; mt < 2; mt++) {
                #pragma unroll
                for (int j = 0; j < 4; j++) {
                    const int ri = mt * 2 + (j & 1);
                    float x = xa[mt*4+j];
                    float e = ex2((x - mr[ri]) * c1r[ri]);
                    zv[ri] += e;
                    vv[ri] = fmaf(e, x, vv[ri]);
                    float h, l;
                    split1(e, h, l);
                    ah[mt][j] = __float_as_uint(h);
                    al[mt][j] = __float_as_uint(l);
                }
            }
            #pragma unroll
            for (int nt = 0; nt < 8; nt++) {
                uint4 bq = *(const uint4*)&B[(nt * 8 + g) * 20 + s * 4 + t];
                #pragma unroll
                for (int mt = 0; mt < 2; mt++) {
                    mma8(acc2[mt][nt], ah[mt], bq.x, bq.y);
                    mma8(acc2[mt][nt], ah[mt], bq.z, bq.w);
                    mma8(acc2[mt][nt], al[mt], bq.x, bq.y);
                }
            }
            #pragma unroll
            for (int j = 0; j < 8; j++) xa[j] = xb[j];
        }
        __syncthreads();
    }

    // z/v butterfly over t lanes
    #pragma unroll
    for (int m = 1; m < 4; m <<= 1) {
        #pragma unroll
        for (int i = 0; i < 4; i++) {
            zv[i] += __shfl_xor_sync(0xffffffffu, zv[i], m);
            vv[i] += __shfl_xor_sync(0xffffffffu, vv[i], m);
        }
    }

    // cross-group reduction in (now dead) buffer smem
    float* Rch = (float*)sb4;                 // 3 x [128][66] for groups 1..3
    float* Zb  = (float*)sb4 + 3 * 128 * 66;  // [4][128]
    float* Vb  = Zb + 512;

    if (t == 0) {
        #pragma unroll
        for (int i = 0; i < 4; i++) {
            Zb[grp * 128 + rows[i]] = zv[i];
            Vb[grp * 128 + rows[i]] = vv[i];
        }
    }
    if (grp > 0) {
        float* Rg = Rch + (grp - 1) * 128 * 66;
        #pragma unroll
        for (int mt = 0; mt < 2; mt++)
            #pragma unroll
            for (int nt = 0; nt < 8; nt++) {
                const int row = wrow + mt * 16 + g, col = nt * 8 + 2 * t;
                *(float2*)&Rg[row * 66 + col]       = make_float2(acc2[mt][nt][0], acc2[mt][nt][1]);
                *(float2*)&Rg[(row + 8) * 66 + col] = make_float2(acc2[mt][nt][2], acc2[mt][nt][3]);
            }
    }
    __syncthreads();

    if (grp == 0) {
        float inv[4];
        #pragma unroll
        for (int i = 0; i < 4; i++) {
            float Z = Zb[rows[i]] + Zb[128 + rows[i]] + Zb[256 + rows[i]] + Zb[384 + rows[i]];
            inv[i] = 1.0f / Z;
            if (t == 0)
                out_v[r0 + rows[i]] =
                    (Vb[rows[i]] + Vb[128 + rows[i]] + Vb[256 + rows[i]] + Vb[384 + rows[i]]) / Z;
        }
        #pragma unroll
        for (int mt = 0; mt < 2; mt++)
            #pragma unroll
            for (int nt = 0; nt < 8; nt++) {
                const int row = wrow + mt * 16 + g, col = nt * 8 + 2 * t;
                float s0 = acc2[mt][nt][0], s1 = acc2[mt][nt][1];
                float s2 = acc2[mt][nt][2], s3 = acc2[mt][nt][3];
                #pragma unroll
                for (int pg = 0; pg < 3; pg++) {
                    const float* Rg = Rch + pg * 128 * 66;
                    float2 p0 = *(const float2*)&Rg[row * 66 + col];
                    float2 p1 = *(const float2*)&Rg[(row + 8) * 66 + col];
                    s0 += p0.x; s1 += p0.y; s2 += p1.x; s3 += p1.y;
                }
                *(float2*)(out_choice + (size_t)(r0 + row) * D_ + col) =
                    make_float2(s0 * inv[mt*2], s1 * inv[mt*2]);
                *(float2*)(out_choice + (size_t)(r0 + row + 8) * D_ + col) =
                    make_float2(s2 * inv[mt*2+1], s3 * inv[mt*2+1]);
            }
    }
}

// ---------------------------------------------------------------------------
extern "C" void kernel_launch(void* const* d_in, const int* in_sizes, int n_in,
                              void* d_out, int out_size) {
    const float* X    = (const float*)d_in[0];
    const float* Yw   = (const float*)d_in[1];
    const float* icpt = (const float*)d_in[2];
    float* out        = (float*)d_out;
    float* out_choice = out;
    float* out_v      = out + (size_t)S_ * D_;

    const int smemG = 2 * 128 * 36 * 16;   // 147,456
    const int smemS = 8 * 1280 * 16;       // 163,840
    cudaFuncSetAttribute(k_gemm1_tc, cudaFuncAttributeMaxDynamicSharedMemorySize, smemG);
    cudaFuncSetAttribute(k_soft,     cudaFuncAttributeMaxDynamicSharedMemorySize, smemS);

    k_prep<<<(NX + NYA + NYT) / 256, 256>>>(X, Yw);

    dim3 g1(K_ / 128, S_ / 128);
    k_gemm1_tc<<<g1, 512, smemG>>>(icpt);
    k_soft<<<S_ / 128, 512, smemS>>>(out_choice, out_v);
}